// round 1
// baseline (speedup 1.0000x reference)
#include <cuda_runtime.h>
#include <math_constants.h>

#define BB 16
#define NN 512
#define Q (BB*NN)   // 8192
#define KNN 8

// ---------------- scratch (static device arrays; no allocation) ----------------
__device__ float g_s1_feat[Q*64];
__device__ float g_s2_feat[Q*128];
__device__ float g_s3_feat[Q*256];
__device__ float g_Y[Q*256];
__device__ float g_G[Q*256];
__device__ float g_Hm[Q*64];
__device__ float g_bufA[Q*3];
__device__ float g_bufB[Q*3];
__device__ int   g_kidx[Q*KNN];
__device__ float g_kd2[Q*KNN];

// ---------------- zero the recurrent state (every call) ----------------
__global__ void zero_states() {
    int i = blockIdx.x*blockDim.x + threadIdx.x;
    int st = gridDim.x*blockDim.x;
    for (int k = i; k < Q*64;  k += st) g_s1_feat[k] = 0.f;
    for (int k = i; k < Q*128; k += st) g_s2_feat[k] = 0.f;
    for (int k = i; k < Q*256; k += st) g_s3_feat[k] = 0.f;
}

// ---------------- knn: top-8 smallest d2, stable tie-break (lower idx first) --
// grid (16 batches, 8 chunks of 64 queries), block 64 threads (1 thread/query)
__global__ void knn_kernel(const float* __restrict__ xyz, int xbs,
                           const float* __restrict__ sxyz, int sbs)
{
    int b = blockIdx.x;
    int n = blockIdx.y * 64 + threadIdx.x;
    __shared__ float4 sp[NN];
    for (int i = threadIdx.x; i < NN; i += 64) {
        const float* p = sxyz + (size_t)b*sbs + i*3;
        sp[i] = make_float4(p[0], p[1], p[2], 0.f);
    }
    __syncthreads();

    const float* qp = xyz + (size_t)b*xbs + n*3;
    float qx = qp[0], qy = qp[1], qz = qp[2];

    float bd[KNN]; int bi[KNN];
#pragma unroll
    for (int i = 0; i < KNN; ++i) { bd[i] = CUDART_INF_F; bi[i] = 0; }

    for (int j = 0; j < NN; ++j) {
        float4 p = sp[j];
        float dx = qx - p.x, dy = qy - p.y, dz = qz - p.z;
        float d2 = dx*dx + dy*dy + dz*dz;
        if (d2 < bd[KNN-1]) {
            bd[KNN-1] = d2; bi[KNN-1] = j;
#pragma unroll
            for (int i = KNN-1; i > 0; --i) {
                if (bd[i] < bd[i-1]) {   // strict: equal keeps lower-index first
                    float td = bd[i]; bd[i] = bd[i-1]; bd[i-1] = td;
                    int   ti = bi[i]; bi[i] = bi[i-1]; bi[i-1] = ti;
                }
            }
        }
    }
    int q = b*NN + n;
#pragma unroll
    for (int i = 0; i < KNN; ++i) {
        g_kd2[q*KNN + i]  = bd[i];
        g_kidx[q*KNN + i] = bi[i];
    }
}

// ---------------- fp32 GEMM: C[M,N] = A[M,K] @ B[K,N] (+bias, opt relu) ------
// BM=128, BN=64, BK=16, 256 threads, 8x4 microtile. M=8192, N%64==0, K%16==0.
template<bool RELU>
__global__ void gemm_kernel(const float* __restrict__ A, int lda,
                            const float* __restrict__ Bm, int ldb,
                            const float* __restrict__ bias,
                            float* __restrict__ C, int ldc, int K)
{
    __shared__ float As[16][132];
    __shared__ float Bs[16][64];
    int tid = threadIdx.x;
    int tx = tid & 15, ty = tid >> 4;
    int bm0 = blockIdx.x * 128;
    int bn0 = blockIdx.y * 64;

    float acc[8][4];
#pragma unroll
    for (int i = 0; i < 8; ++i)
#pragma unroll
        for (int j = 0; j < 4; ++j) acc[i][j] = 0.f;

    int la_c = tid & 15;   // k within tile
    int la_r = tid >> 4;   // m base
    int lb_c = tid & 63;   // n
    int lb_r = tid >> 6;   // k base

    for (int k0 = 0; k0 < K; k0 += 16) {
#pragma unroll
        for (int r = 0; r < 8; ++r)
            As[la_c][la_r + 16*r] =
                A[(size_t)(bm0 + la_r + 16*r)*lda + k0 + la_c];
#pragma unroll
        for (int r = 0; r < 4; ++r)
            Bs[lb_r + 4*r][lb_c] =
                Bm[(size_t)(k0 + lb_r + 4*r)*ldb + bn0 + lb_c];
        __syncthreads();
#pragma unroll
        for (int kk = 0; kk < 16; ++kk) {
            float4 a0 = *reinterpret_cast<const float4*>(&As[kk][ty*8]);
            float4 a1 = *reinterpret_cast<const float4*>(&As[kk][ty*8 + 4]);
            float4 bf = *reinterpret_cast<const float4*>(&Bs[kk][tx*4]);
            float a[8] = {a0.x,a0.y,a0.z,a0.w,a1.x,a1.y,a1.z,a1.w};
            float bb[4] = {bf.x,bf.y,bf.z,bf.w};
#pragma unroll
            for (int i = 0; i < 8; ++i)
#pragma unroll
                for (int j = 0; j < 4; ++j)
                    acc[i][j] = fmaf(a[i], bb[j], acc[i][j]);
        }
        __syncthreads();
    }

    float bv[4] = {0.f,0.f,0.f,0.f};
    if (bias) {
#pragma unroll
        for (int j = 0; j < 4; ++j) bv[j] = bias[bn0 + tx*4 + j];
    }
#pragma unroll
    for (int i = 0; i < 8; ++i) {
        int row = bm0 + ty*8 + i;
        float4 v;
        float* vp = &v.x;
#pragma unroll
        for (int j = 0; j < 4; ++j) {
            float t = acc[i][j] + bv[j];
            if (RELU) t = fmaxf(t, 0.f);
            vp[j] = t;
        }
        *reinterpret_cast<float4*>(&C[(size_t)row*ldc + bn0 + tx*4]) = v;
    }
}

// ---------------- fused gather + disp-matmul + max + add ----------------
// out[q,c] = max_k( disp_k . Wd[:,c] + Y[b, j_k, c] ) + (G ? G[q,c] : bias[c])
template<int COUT>
__global__ void fuse_kernel(const float* __restrict__ xyz, int xbs,
                            const float* __restrict__ sxyz, int sbs,
                            const float* __restrict__ Y,
                            const float* __restrict__ G,
                            const float* __restrict__ Wd,
                            const float* __restrict__ bias,
                            float r2,
                            float* __restrict__ out)
{
    int q = blockIdx.x;
    int b = q >> 9, n = q & 511;
    __shared__ int sj[KNN];
    __shared__ float sdisp[KNN][3];
    int t = threadIdx.x;
    if (t < KNN) {
        int i0 = g_kidx[q*KNN];
        float d2 = g_kd2[q*KNN + t];
        int i  = g_kidx[q*KNN + t];
        sj[t] = (d2 <= r2) ? i : i0;
    }
    __syncthreads();
    if (t < KNN*3) {
        int k = t / 3, d = t % 3;
        sdisp[k][d] = sxyz[(size_t)b*sbs + sj[k]*3 + d]
                    - xyz[(size_t)b*xbs + n*3 + d];
    }
    __syncthreads();

    float w0 = Wd[t], w1 = Wd[COUT + t], w2 = Wd[2*COUT + t];
    const float* Yb = Y + (size_t)b*NN*COUT;
    float m = -CUDART_INF_F;
#pragma unroll
    for (int k = 0; k < KNN; ++k) {
        float v = sdisp[k][0]*w0 + sdisp[k][1]*w1 + sdisp[k][2]*w2
                + Yb[(size_t)sj[k]*COUT + t];
        m = fmaxf(m, v);
    }
    float g = G ? G[(size_t)q*COUT + t] : bias[t];
    out[(size_t)q*COUT + t] = m + g;
}

// ---------------- motion: mot = Hm@Wl + bl; nxt = cur + mot; preds[j] = nxt --
__global__ void motion_kernel(const float* __restrict__ Wl,
                              const float* __restrict__ bl,
                              const float* __restrict__ cur, int cbs,
                              float* __restrict__ nxt,
                              float* __restrict__ preds, int j)
{
    int q = blockIdx.x * blockDim.x + threadIdx.x;
    if (q >= Q) return;
    int b = q >> 9, n = q & 511;
    float m0 = bl[0], m1 = bl[1], m2 = bl[2];
    const float* h = g_Hm + (size_t)q*64;
#pragma unroll
    for (int k = 0; k < 64; ++k) {
        float hv = h[k];
        m0 = fmaf(hv, Wl[k*3+0], m0);
        m1 = fmaf(hv, Wl[k*3+1], m1);
        m2 = fmaf(hv, Wl[k*3+2], m2);
    }
    const float* c = cur + (size_t)b*cbs + n*3;
    float x = c[0] + m0, y = c[1] + m1, z = c[2] + m2;
    float* np = nxt + (size_t)q*3;
    np[0] = x; np[1] = y; np[2] = z;
    float* o = preds + ((size_t)(b*6 + j)*NN + n)*3;
    o[0] = x; o[1] = y; o[2] = z;
}

// ---------------- host orchestration ----------------
extern "C" void kernel_launch(void* const* d_in, const int* in_sizes, int n_in,
                              void* d_out, int out_size)
{
    const float* frames = (const float*)d_in[0];
    const float* W1 = (const float*)d_in[1];
    const float* b1 = (const float*)d_in[2];
    const float* W2 = (const float*)d_in[3];
    const float* b2 = (const float*)d_in[4];
    const float* W3 = (const float*)d_in[5];
    const float* b3 = (const float*)d_in[6];
    const float* Wm = (const float*)d_in[7];
    const float* bm = (const float*)d_in[8];
    const float* Wl = (const float*)d_in[9];
    const float* bl = (const float*)d_in[10];
    float* out = (float*)d_out;

    float *s1f, *s2f, *s3f, *Yb, *Gb, *Hb, *bufA, *bufB;
    cudaGetSymbolAddress((void**)&s1f,  g_s1_feat);
    cudaGetSymbolAddress((void**)&s2f,  g_s2_feat);
    cudaGetSymbolAddress((void**)&s3f,  g_s3_feat);
    cudaGetSymbolAddress((void**)&Yb,   g_Y);
    cudaGetSymbolAddress((void**)&Gb,   g_G);
    cudaGetSymbolAddress((void**)&Hb,   g_Hm);
    cudaGetSymbolAddress((void**)&bufA, g_bufA);
    cudaGetSymbolAddress((void**)&bufB, g_bufB);

    zero_states<<<512, 256>>>();

    const int FBS = 12*NN*3;  // per-batch stride inside frames
    const float R2_1 = (float)(4.000001*4.000001);
    const float R2_2 = (float)(8.000001*8.000001);
    const float R2_3 = (float)(12.000001*12.000001);

    for (int step = 0; step < 12; ++step) {
        const float *cur, *prev; int cbs, pbs;
        if (step < 6) {
            cur = frames + step*NN*3;                  cbs = FBS;
            prev = frames + (step > 0 ? step-1 : 0)*NN*3; pbs = FBS;
        } else {
            int j = step - 6;
            if (j == 0)      { cur = frames + 5*NN*3; cbs = FBS; }
            else             { cur = (j & 1) ? bufA : bufB; cbs = NN*3; }
            if (j <= 1)      { prev = frames + 5*NN*3; pbs = FBS; }
            else             { prev = (j & 1) ? bufB : bufA; pbs = NN*3; }
        }

        knn_kernel<<<dim3(16, 8), 64>>>(cur, cbs, prev, pbs);

        // ---- cell 1: fin = 3 + 64, cout 64 ----
        gemm_kernel<false><<<dim3(64,1), 256>>>(s1f, 64, W1 + 3*64, 64,
                                                nullptr, Yb, 64, 64);
        fuse_kernel<64><<<Q, 64>>>(cur, cbs, prev, pbs, Yb, nullptr,
                                   W1, b1, R2_1, s1f);

        // ---- cell 2: fin = 3 + 64 + 128, cout 128 ----
        gemm_kernel<false><<<dim3(64,2), 256>>>(s2f, 128, W2 + 67*128, 128,
                                                nullptr, Yb, 128, 128);
        gemm_kernel<false><<<dim3(64,2), 256>>>(s1f, 64, W2 + 3*128, 128,
                                                b2, Gb, 128, 64);
        fuse_kernel<128><<<Q, 128>>>(cur, cbs, prev, pbs, Yb, Gb,
                                     W2, b2, R2_2, s2f);

        // ---- cell 3: fin = 3 + 128 + 256, cout 256 ----
        gemm_kernel<false><<<dim3(64,4), 256>>>(s3f, 256, W3 + 131*256, 256,
                                                nullptr, Yb, 256, 256);
        gemm_kernel<false><<<dim3(64,4), 256>>>(s2f, 128, W3 + 3*256, 256,
                                                b3, Gb, 256, 128);
        fuse_kernel<256><<<Q, 256>>>(cur, cbs, prev, pbs, Yb, Gb,
                                     W3, b3, R2_3, s3f);

        if (step >= 6) {
            int j = step - 6;
            float* nxt = (j & 1) ? bufB : bufA;
            gemm_kernel<true><<<dim3(64,1), 256>>>(s3f, 256, Wm, 64,
                                                   bm, Hb, 64, 256);
            motion_kernel<<<64, 128>>>(Wl, bl, cur, cbs, nxt, out, j);
        }
    }
}

// round 3
// speedup vs baseline: 1.7880x; 1.7880x over previous
#include <cuda_runtime.h>
#include <math_constants.h>

#define BB 16
#define NN 512
#define Q (BB*NN)   // 8192
#define KNN 8

// ---------------- scratch ----------------
__device__ float g_s1_feat[Q*64];
__device__ float g_s2_feat[Q*128];
__device__ float g_s3_feat[Q*256];
__device__ float g_Y[Q*256];
__device__ float g_G[Q*256];
__device__ float g_Hm[Q*64];
__device__ float g_bufA[Q*3];
__device__ float g_bufB[Q*3];
__device__ int   g_kidx[Q*KNN];
__device__ float g_kd2[Q*KNN];

__global__ void zero_states() {
    int i = blockIdx.x*blockDim.x + threadIdx.x;
    int st = gridDim.x*blockDim.x;
    for (int k = i; k < Q*64;  k += st) g_s1_feat[k] = 0.f;
    for (int k = i; k < Q*128; k += st) g_s2_feat[k] = 0.f;
    for (int k = i; k < Q*256; k += st) g_s3_feat[k] = 0.f;
}

// ---------------- knn: 4 threads/query over point partitions + merge --------
__global__ void knn2(const float* __restrict__ xyz, int xbs,
                     const float* __restrict__ sxyz, int sbs)
{
    __shared__ float4 sp[NN];
    __shared__ float candd[64][33];
    __shared__ int   candi[64][33];
    int b = blockIdx.x;
    int tid = threadIdx.x;
    for (int i = tid; i < NN; i += 256) {
        const float* p = sxyz + (size_t)b*sbs + i*3;
        sp[i] = make_float4(p[0], p[1], p[2], 0.f);
    }
    __syncthreads();

    int qi = tid >> 2, tq = tid & 3;
    int n = blockIdx.y*64 + qi;
    const float* qp = xyz + (size_t)b*xbs + n*3;
    float qx = qp[0], qy = qp[1], qz = qp[2];

    float bd[KNN]; int bi[KNN];
#pragma unroll
    for (int i = 0; i < KNN; ++i) { bd[i] = CUDART_INF_F; bi[i] = 0; }

    int j0 = tq*128;
    for (int j = j0; j < j0+128; ++j) {
        float4 p = sp[j];
        float dx = qx - p.x, dy = qy - p.y, dz = qz - p.z;
        float d2 = dx*dx + dy*dy + dz*dz;
        if (d2 < bd[KNN-1]) {
            bd[KNN-1] = d2; bi[KNN-1] = j;
#pragma unroll
            for (int i = KNN-1; i > 0; --i) {
                if (bd[i] < bd[i-1]) {
                    float td = bd[i]; bd[i] = bd[i-1]; bd[i-1] = td;
                    int   ti = bi[i]; bi[i] = bi[i-1]; bi[i-1] = ti;
                }
            }
        }
    }
#pragma unroll
    for (int s = 0; s < KNN; ++s) {
        candd[qi][tq*8 + s] = bd[s];
        candi[qi][tq*8 + s] = bi[s];
    }
    __syncthreads();

    if (tid < 64) {
        int q = b*NN + blockIdx.y*64 + tid;
        int p[4] = {0,0,0,0};
        for (int s = 0; s < KNN; ++s) {
            float best = CUDART_INF_F; int bl = 0;
#pragma unroll
            for (int l = 0; l < 4; ++l) {
                int pi = p[l];
                float d = (pi < 8) ? candd[tid][l*8 + pi] : CUDART_INF_F;
                if (d < best) { best = d; bl = l; }
            }
            g_kd2[q*KNN + s]  = best;
            g_kidx[q*KNN + s] = candi[tid][bl*8 + p[bl]];
            p[bl]++;
        }
    }
}

// ---------------- fp32 GEMM v2: double-buffered, full K unroll ---------------
// C[M,N] = A[M,K] @ B[K,N] (+bias, opt relu). BN=64, BK=16, BM template.
template<int BM, int KDIM, bool RELU>
__global__ void __launch_bounds__(BM*2)
gemm2(const float* __restrict__ A, int lda,
      const float* __restrict__ Bm, int ldb,
      const float* __restrict__ bias,
      float* __restrict__ C, int ldc)
{
    constexpr int THREADS = BM*2;
    constexpr int KT = KDIM/16;
    constexpr int APAD = (BM == 128) ? 132 : 68;
    constexpr int NB = 256/THREADS;      // B-tile float4s per thread
    __shared__ float As[2][16][APAD];
    __shared__ float Bs[2][16][64];
    int tid = threadIdx.x;
    int tx = tid & 15, ty = tid >> 4;
    int bm0 = blockIdx.x * BM, bn0 = blockIdx.y * 64;

    float acc[8][4];
#pragma unroll
    for (int i = 0; i < 8; ++i)
#pragma unroll
        for (int j = 0; j < 4; ++j) acc[i][j] = 0.f;

    float4 ra[2];
    float4 rb[NB];

    auto ldg = [&](int kt) {
#pragma unroll
        for (int i = 0; i < 2; ++i) {
            int idx = tid + i*THREADS;
            int row = idx >> 2, ks = idx & 3;
            ra[i] = *reinterpret_cast<const float4*>(
                        &A[(size_t)(bm0 + row)*lda + kt*16 + ks*4]);
        }
#pragma unroll
        for (int i = 0; i < NB; ++i) {
            int idx = tid + i*THREADS;
            int kk = idx >> 4, n4 = idx & 15;
            rb[i] = *reinterpret_cast<const float4*>(
                        &Bm[(size_t)(kt*16 + kk)*ldb + bn0 + n4*4]);
        }
    };
    auto sts = [&](int buf) {
#pragma unroll
        for (int i = 0; i < 2; ++i) {
            int idx = tid + i*THREADS;
            int row = idx >> 2, ks = idx & 3;
            As[buf][ks*4+0][row] = ra[i].x;
            As[buf][ks*4+1][row] = ra[i].y;
            As[buf][ks*4+2][row] = ra[i].z;
            As[buf][ks*4+3][row] = ra[i].w;
        }
#pragma unroll
        for (int i = 0; i < NB; ++i) {
            int idx = tid + i*THREADS;
            int kk = idx >> 4, n4 = idx & 15;
            *reinterpret_cast<float4*>(&Bs[buf][kk][n4*4]) = rb[i];
        }
    };

    ldg(0); sts(0); __syncthreads();
    int buf = 0;
#pragma unroll
    for (int kt = 0; kt < KT; ++kt) {
        if (kt + 1 < KT) ldg(kt + 1);
#pragma unroll
        for (int kk = 0; kk < 16; ++kk) {
            float4 a0 = *reinterpret_cast<const float4*>(&As[buf][kk][ty*8]);
            float4 a1 = *reinterpret_cast<const float4*>(&As[buf][kk][ty*8+4]);
            float4 bf = *reinterpret_cast<const float4*>(&Bs[buf][kk][tx*4]);
            float av[8] = {a0.x,a0.y,a0.z,a0.w,a1.x,a1.y,a1.z,a1.w};
            float bv[4] = {bf.x,bf.y,bf.z,bf.w};
#pragma unroll
            for (int i = 0; i < 8; ++i)
#pragma unroll
                for (int j = 0; j < 4; ++j)
                    acc[i][j] = fmaf(av[i], bv[j], acc[i][j]);
        }
        if (kt + 1 < KT) { sts(buf ^ 1); __syncthreads(); buf ^= 1; }
    }

    float bv[4] = {0.f,0.f,0.f,0.f};
    if (bias) {
#pragma unroll
        for (int j = 0; j < 4; ++j) bv[j] = bias[bn0 + tx*4 + j];
    }
#pragma unroll
    for (int i = 0; i < 8; ++i) {
        int row = bm0 + ty*8 + i;
        float4 v;
        float* vp = &v.x;
#pragma unroll
        for (int j = 0; j < 4; ++j) {
            float t = acc[i][j] + bv[j];
            if (RELU) t = fmaxf(t, 0.f);
            vp[j] = t;
        }
        *reinterpret_cast<float4*>(&C[(size_t)row*ldc + bn0 + tx*4]) = v;
    }
}

// ---------------- fused gather + disp-matmul + max + add --------------------
template<int COUT>
__global__ void __launch_bounds__(512)
fuse2(const float* __restrict__ xyz, int xbs,
      const float* __restrict__ sxyz, int sbs,
      const float* __restrict__ Y,
      const float* __restrict__ G,
      const float* __restrict__ Wd,
      const float* __restrict__ bias,
      float r2,
      float* __restrict__ out)
{
    constexpr int QPB = 512/COUT;
    __shared__ int sj[QPB][KNN];
    __shared__ float sdisp[QPB][KNN][3];
    int t = threadIdx.x;
    int q0 = blockIdx.x * QPB;

    if (t < QPB*KNN) {
        int qi = t >> 3, k = t & 7;
        int q = q0 + qi;
        float d2 = g_kd2[q*KNN + k];
        int i  = g_kidx[q*KNN + k];
        int i0 = g_kidx[q*KNN];
        sj[qi][k] = (d2 <= r2) ? i : i0;
    }
    __syncthreads();
    if (t < QPB*KNN*3) {
        int qi = t/24, r = t - qi*24, k = r/3, d = r - k*3;
        int q = q0 + qi; int b = q >> 9, n = q & 511;
        sdisp[qi][k][d] = sxyz[(size_t)b*sbs + sj[qi][k]*3 + d]
                        - xyz[(size_t)b*xbs + n*3 + d];
    }
    __syncthreads();

    int qi = t / COUT, c = t % COUT;
    int q = q0 + qi, b = q >> 9;
    float w0 = Wd[c], w1 = Wd[COUT + c], w2 = Wd[2*COUT + c];
    const float* Yb = Y + (size_t)b*NN*COUT;
    float m = -CUDART_INF_F;
#pragma unroll
    for (int k = 0; k < KNN; ++k) {
        int j = sj[qi][k];
        float v = sdisp[qi][k][0]*w0 + sdisp[qi][k][1]*w1 + sdisp[qi][k][2]*w2
                + Yb[(size_t)j*COUT + c];
        m = fmaxf(m, v);
    }
    float g = G ? G[(size_t)q*COUT + c] : bias[c];
    out[(size_t)q*COUT + c] = m + g;
}

// ---------------- motion ----------------------------------------------------
__global__ void motion_kernel(const float* __restrict__ Wl,
                              const float* __restrict__ bl,
                              const float* __restrict__ cur, int cbs,
                              float* __restrict__ nxt,
                              float* __restrict__ preds, int j)
{
    int q = blockIdx.x * blockDim.x + threadIdx.x;
    if (q >= Q) return;
    int b = q >> 9, n = q & 511;
    float m0 = bl[0], m1 = bl[1], m2 = bl[2];
    const float* h = g_Hm + (size_t)q*64;
#pragma unroll
    for (int k = 0; k < 64; ++k) {
        float hv = h[k];
        m0 = fmaf(hv, Wl[k*3+0], m0);
        m1 = fmaf(hv, Wl[k*3+1], m1);
        m2 = fmaf(hv, Wl[k*3+2], m2);
    }
    const float* c = cur + (size_t)b*cbs + n*3;
    float x = c[0] + m0, y = c[1] + m1, z = c[2] + m2;
    float* np = nxt + (size_t)q*3;
    np[0] = x; np[1] = y; np[2] = z;
    float* o = preds + ((size_t)(b*6 + j)*NN + n)*3;
    o[0] = x; o[1] = y; o[2] = z;
}

// ---------------- host orchestration ----------------------------------------
extern "C" void kernel_launch(void* const* d_in, const int* in_sizes, int n_in,
                              void* d_out, int out_size)
{
    const float* frames = (const float*)d_in[0];
    const float* W1 = (const float*)d_in[1];
    const float* b1 = (const float*)d_in[2];
    const float* W2 = (const float*)d_in[3];
    const float* b2 = (const float*)d_in[4];
    const float* W3 = (const float*)d_in[5];
    const float* b3 = (const float*)d_in[6];
    const float* Wm = (const float*)d_in[7];
    const float* bm = (const float*)d_in[8];
    const float* Wl = (const float*)d_in[9];
    const float* bl = (const float*)d_in[10];
    float* out = (float*)d_out;

    float *s1f, *s2f, *s3f, *Yb, *Gb, *Hb, *bufA, *bufB;
    cudaGetSymbolAddress((void**)&s1f,  g_s1_feat);
    cudaGetSymbolAddress((void**)&s2f,  g_s2_feat);
    cudaGetSymbolAddress((void**)&s3f,  g_s3_feat);
    cudaGetSymbolAddress((void**)&Yb,   g_Y);
    cudaGetSymbolAddress((void**)&Gb,   g_G);
    cudaGetSymbolAddress((void**)&Hb,   g_Hm);
    cudaGetSymbolAddress((void**)&bufA, g_bufA);
    cudaGetSymbolAddress((void**)&bufB, g_bufB);

    zero_states<<<512, 256>>>();

    const int FBS = 12*NN*3;
    const float R2_1 = (float)(4.000001*4.000001);
    const float R2_2 = (float)(8.000001*8.000001);
    const float R2_3 = (float)(12.000001*12.000001);

    for (int step = 0; step < 12; ++step) {
        const float *cur, *prev; int cbs, pbs;
        if (step < 6) {
            cur = frames + step*NN*3;                     cbs = FBS;
            prev = frames + (step > 0 ? step-1 : 0)*NN*3; pbs = FBS;
        } else {
            int j = step - 6;
            if (j == 0) { cur = frames + 5*NN*3; cbs = FBS; }
            else        { cur = (j & 1) ? bufA : bufB; cbs = NN*3; }
            if (j <= 1) { prev = frames + 5*NN*3; pbs = FBS; }
            else        { prev = (j & 1) ? bufB : bufA; pbs = NN*3; }
        }

        knn2<<<dim3(16, 8), 256>>>(cur, cbs, prev, pbs);

        // ---- cell 1: cout 64 ----
        gemm2<64,64,false><<<dim3(128,1), 128>>>(s1f, 64, W1 + 3*64, 64,
                                                 nullptr, Yb, 64);
        fuse2<64><<<1024, 512>>>(cur, cbs, prev, pbs, Yb, nullptr,
                                 W1, b1, R2_1, s1f);

        // ---- cell 2: cout 128 ----
        gemm2<128,128,false><<<dim3(64,2), 256>>>(s2f, 128, W2 + 67*128, 128,
                                                  nullptr, Yb, 128);
        gemm2<128,64,false><<<dim3(64,2), 256>>>(s1f, 64, W2 + 3*128, 128,
                                                 b2, Gb, 128);
        fuse2<128><<<2048, 512>>>(cur, cbs, prev, pbs, Yb, Gb,
                                  W2, b2, R2_2, s2f);

        // ---- cell 3: cout 256 ----
        gemm2<128,256,false><<<dim3(64,4), 256>>>(s3f, 256, W3 + 131*256, 256,
                                                  nullptr, Yb, 256);
        gemm2<128,128,false><<<dim3(64,4), 256>>>(s2f, 128, W3 + 3*256, 256,
                                                  b3, Gb, 256);
        fuse2<256><<<4096, 512>>>(cur, cbs, prev, pbs, Yb, Gb,
                                  W3, b3, R2_3, s3f);

        if (step >= 6) {
            int j = step - 6;
            float* nxt = (j & 1) ? bufB : bufA;
            gemm2<64,256,true><<<dim3(128,1), 128>>>(s3f, 256, Wm, 64,
                                                     bm, Hb, 64);
            motion_kernel<<<32, 256>>>(Wl, bl, cur, cbs, nxt, out, j);
        }
    }
}